// round 14
// baseline (speedup 1.0000x reference)
#include <cuda_runtime.h>
#include <math_constants.h>

// ---------------- problem constants (fixed shapes) ----------------
#define N_NODES  8192
#define N_EDGES  262144
#define IN_C     64
#define DIN      192          // IN_C * K
#define DOUT     192          // OUT_C * K
#define G_GRAPHS 64
#define D3       576          // 3 * DOUT
#define H1DIM    384
#define H2DIM    192
#define NCLS     10
#define BN_EPS   1e-5f

// ---------------- device scratch ----------------
__device__ float g_deg[N_NODES];        // zeroed by funnel tail
__device__ int   g_rowCnt[N_NODES];     // zeroed by funnel tail
__device__ float g_dinv[N_NODES];
__device__ int   g_rowPtr[N_NODES + 1];
__device__ unsigned long long g_cv[N_EDGES];   // packed (val<<32 | col)
__device__ float g_Hcat[N_NODES * DIN]; // [x | Lx | L^2 x]
__device__ float g_HT[DOUT * N_NODES];  // H transposed: [col][node]
__device__ float g_sigma;
__device__ float4 g_pool[G_GRAPHS * DOUT]; // per (graph,col): {sum, sumsq, max, min}

// ---------------- kernels ----------------

__global__ void k_degree(const int* __restrict__ ei) {
    int e = blockIdx.x * blockDim.x + threadIdx.x;
    if (e < N_EDGES) atomicAdd(&g_deg[ei[e]], 1.0f);
}

// dinv + exclusive scan (warp-shuffle) + spectral sigma, one block of 1024
__global__ void k_scan(const float* __restrict__ W, const float* __restrict__ u) {
    __shared__ int   wsum[32];
    __shared__ float fred[256];
    __shared__ float vpart[5][DIN];
    int t = threadIdx.x, lane = t & 31, wid = t >> 5;
    int base = t * 8;
    int loc[8]; int s = 0;
#pragma unroll
    for (int j = 0; j < 8; ++j) {
        float d = g_deg[base + j];
        g_dinv[base + j] = (d > 0.f) ? rsqrtf(fmaxf(d, 1.f)) : 0.f;
        loc[j] = s; s += (int)d;
    }
    int isc = s;
#pragma unroll
    for (int off = 1; off < 32; off <<= 1) {
        int v = __shfl_up_sync(0xffffffff, isc, off);
        if (lane >= off) isc += v;
    }
    if (lane == 31) wsum[wid] = isc;
    __syncthreads();
    if (wid == 0) {
        int v = wsum[lane];
        int sc = v;
#pragma unroll
        for (int off = 1; off < 32; off <<= 1) {
            int q = __shfl_up_sync(0xffffffff, sc, off);
            if (lane >= off) sc += q;
        }
        wsum[lane] = sc - v;
    }
    __syncthreads();
    int tbase = wsum[wid] + (isc - s);
#pragma unroll
    for (int j = 0; j < 8; ++j) g_rowPtr[base + j] = tbase + loc[j];
    if (t == 1023) g_rowPtr[N_NODES] = tbase + s;

    // sigma = ||W^T u||^2 / (||W^T u|| + 1e-12); 960 threads, 5-way row split
    if (t < 960) {
        int g = t / DIN, c = t % DIN;
        float a = 0.f;
        for (int i = g; i < DOUT; i += 5)
            a = fmaf(W[i * DIN + c], __ldg(&u[i]), a);
        vpart[g][c] = a;
    }
    __syncthreads();
    float vsq = 0.f;
    if (t < DIN) {
        float v = vpart[0][t] + vpart[1][t] + vpart[2][t] + vpart[3][t] + vpart[4][t];
        vsq = v * v;
    }
    if (t < 256) fred[t] = vsq;
    __syncthreads();
    for (int off = 128; off; off >>= 1) {
        if (t < 256 && t < off) fred[t] += fred[t + off];
        __syncthreads();
    }
    if (t == 0) {
        float ns = fred[0];
        g_sigma = ns / (sqrtf(ns) + 1e-12f);
    }
}

// CSR fill: one packed 8B store per edge
__global__ void k_build(const int* __restrict__ ei) {
    int e = blockIdx.x * blockDim.x + threadIdx.x;
    if (e >= N_EDGES) return;
    int r = ei[e];
    int c = ei[N_EDGES + e];
    float v = -g_dinv[r] * g_dinv[c];
    int pos = g_rowPtr[r] + atomicAdd(&g_rowCnt[r], 1);
    g_cv[pos] = ((unsigned long long)__float_as_uint(v) << 32) | (unsigned int)c;
}

// SpMM row body: 8-deep software pipeline (8 cv loads + 8 gathers in flight,
// next group's cv loads issued before current gathers complete).
template <int STRIDE>
__device__ __forceinline__ float2 spmm_row(const float* __restrict__ src,
                                           float2 acc, int s, int e) {
    int p = s;
    int n8 = (e - s) >> 3;
    if (n8 > 0) {
        unsigned long long a0 = __ldg(&g_cv[p]),     a1 = __ldg(&g_cv[p + 1]);
        unsigned long long a2 = __ldg(&g_cv[p + 2]), a3 = __ldg(&g_cv[p + 3]);
        unsigned long long a4 = __ldg(&g_cv[p + 4]), a5 = __ldg(&g_cv[p + 5]);
        unsigned long long a6 = __ldg(&g_cv[p + 6]), a7 = __ldg(&g_cv[p + 7]);
        for (int q = 0; q < n8; ++q) {
            unsigned long long b0 = a0, b1 = a1, b2 = a2, b3 = a3;
            unsigned long long b4 = a4, b5 = a5, b6 = a6, b7 = a7;
            p += 8;
            if (q + 1 < n8) {
                a0 = __ldg(&g_cv[p]);     a1 = __ldg(&g_cv[p + 1]);
                a2 = __ldg(&g_cv[p + 2]); a3 = __ldg(&g_cv[p + 3]);
                a4 = __ldg(&g_cv[p + 4]); a5 = __ldg(&g_cv[p + 5]);
                a6 = __ldg(&g_cv[p + 6]); a7 = __ldg(&g_cv[p + 7]);
            }
            float2 x0 = *(const float2*)&src[(int)(b0 & 0xffffffffu) * STRIDE];
            float2 x1 = *(const float2*)&src[(int)(b1 & 0xffffffffu) * STRIDE];
            float2 x2 = *(const float2*)&src[(int)(b2 & 0xffffffffu) * STRIDE];
            float2 x3 = *(const float2*)&src[(int)(b3 & 0xffffffffu) * STRIDE];
            float2 x4 = *(const float2*)&src[(int)(b4 & 0xffffffffu) * STRIDE];
            float2 x5 = *(const float2*)&src[(int)(b5 & 0xffffffffu) * STRIDE];
            float2 x6 = *(const float2*)&src[(int)(b6 & 0xffffffffu) * STRIDE];
            float2 x7 = *(const float2*)&src[(int)(b7 & 0xffffffffu) * STRIDE];
            float v0 = __uint_as_float((unsigned)(b0 >> 32));
            float v1 = __uint_as_float((unsigned)(b1 >> 32));
            float v2 = __uint_as_float((unsigned)(b2 >> 32));
            float v3 = __uint_as_float((unsigned)(b3 >> 32));
            float v4 = __uint_as_float((unsigned)(b4 >> 32));
            float v5 = __uint_as_float((unsigned)(b5 >> 32));
            float v6 = __uint_as_float((unsigned)(b6 >> 32));
            float v7 = __uint_as_float((unsigned)(b7 >> 32));
            acc.x = fmaf(v0, x0.x, acc.x); acc.y = fmaf(v0, x0.y, acc.y);
            acc.x = fmaf(v1, x1.x, acc.x); acc.y = fmaf(v1, x1.y, acc.y);
            acc.x = fmaf(v2, x2.x, acc.x); acc.y = fmaf(v2, x2.y, acc.y);
            acc.x = fmaf(v3, x3.x, acc.x); acc.y = fmaf(v3, x3.y, acc.y);
            acc.x = fmaf(v4, x4.x, acc.x); acc.y = fmaf(v4, x4.y, acc.y);
            acc.x = fmaf(v5, x5.x, acc.x); acc.y = fmaf(v5, x5.y, acc.y);
            acc.x = fmaf(v6, x6.x, acc.x); acc.y = fmaf(v6, x6.y, acc.y);
            acc.x = fmaf(v7, x7.x, acc.x); acc.y = fmaf(v7, x7.y, acc.y);
        }
    }
    if (p + 3 < e) {
        unsigned long long b0 = __ldg(&g_cv[p]),     b1 = __ldg(&g_cv[p + 1]);
        unsigned long long b2 = __ldg(&g_cv[p + 2]), b3 = __ldg(&g_cv[p + 3]);
        p += 4;
        float2 x0 = *(const float2*)&src[(int)(b0 & 0xffffffffu) * STRIDE];
        float2 x1 = *(const float2*)&src[(int)(b1 & 0xffffffffu) * STRIDE];
        float2 x2 = *(const float2*)&src[(int)(b2 & 0xffffffffu) * STRIDE];
        float2 x3 = *(const float2*)&src[(int)(b3 & 0xffffffffu) * STRIDE];
        float v0 = __uint_as_float((unsigned)(b0 >> 32));
        float v1 = __uint_as_float((unsigned)(b1 >> 32));
        float v2 = __uint_as_float((unsigned)(b2 >> 32));
        float v3 = __uint_as_float((unsigned)(b3 >> 32));
        acc.x = fmaf(v0, x0.x, acc.x); acc.y = fmaf(v0, x0.y, acc.y);
        acc.x = fmaf(v1, x1.x, acc.x); acc.y = fmaf(v1, x1.y, acc.y);
        acc.x = fmaf(v2, x2.x, acc.x); acc.y = fmaf(v2, x2.y, acc.y);
        acc.x = fmaf(v3, x3.x, acc.x); acc.y = fmaf(v3, x3.y, acc.y);
    }
    for (; p < e; ++p) {
        unsigned long long cv = __ldg(&g_cv[p]);
        float v = __uint_as_float((unsigned)(cv >> 32));
        float2 a = *(const float2*)&src[(int)(cv & 0xffffffffu) * STRIDE];
        acc.x = fmaf(v, a.x, acc.x); acc.y = fmaf(v, a.y, acc.y);
    }
    return acc;
}

// hop 1: Hcat[:,0:64]=x, Hcat[:,64:128]=x+L_off@x  (warp/row)
__global__ void k_spmm1(const float* __restrict__ x) {
    int w = (blockIdx.x * blockDim.x + threadIdx.x) >> 5;
    int lane = threadIdx.x & 31;
    const float* src = &x[2 * lane];
    float2 xv0 = *(const float2*)&src[w * 64];
    float2 acc = spmm_row<64>(src, xv0, g_rowPtr[w], g_rowPtr[w + 1]);
    *(float2*)&g_Hcat[w * DIN + 2 * lane]      = xv0;
    *(float2*)&g_Hcat[w * DIN + 64 + 2 * lane] = acc;
}

// hop 2: src = Hcat[:,64:128], dst = Hcat[:,128:192]
__global__ void k_spmm2() {
    int w = (blockIdx.x * blockDim.x + threadIdx.x) >> 5;
    int lane = threadIdx.x & 31;
    const float* src = &g_Hcat[64 + 2 * lane];
    float2 acc0 = *(const float2*)&src[w * DIN];
    float2 acc = spmm_row<DIN>(src, acc0, g_rowPtr[w], g_rowPtr[w + 1]);
    *(float2*)&g_Hcat[w * DIN + 128 + 2 * lane] = acc;
}

// H^T = (Hcat @ (mask(W)/sigma)^T + b)^T, mask folded into Klim.
// 64x64 tiles, float4 shared reads, transposed float4 stores. No atomics.
__global__ void k_gemm(const float* __restrict__ W, const float* __restrict__ bias) {
    const int m0 = blockIdx.x * 64;
    const int n0 = blockIdx.y * 64;
    const int Klim = 64 * (blockIdx.y + 1);
    __shared__ float As[32][68];
    __shared__ float Bs[32][68];
    const int tid = threadIdx.x;                // 256
    const int tx = tid & 15, ty = tid >> 4;
    const float invSig = 1.0f / g_sigma;
    float acc[4][4] = {};
    for (int k0 = 0; k0 < Klim; k0 += 32) {
#pragma unroll
        for (int r = 0; r < 8; ++r) {
            int e = tid + r * 256;
            int m = e >> 5, k = e & 31;
            As[k][m] = g_Hcat[(m0 + m) * DIN + k0 + k];
            Bs[k][m] = W[(n0 + m) * DIN + k0 + k] * invSig;
        }
        __syncthreads();
#pragma unroll
        for (int k = 0; k < 32; ++k) {
            float4 av = *(const float4*)&As[k][ty * 4];
            float4 bv = *(const float4*)&Bs[k][tx * 4];
            float a[4] = {av.x, av.y, av.z, av.w};
            float bb[4] = {bv.x, bv.y, bv.z, bv.w};
#pragma unroll
            for (int i = 0; i < 4; ++i)
#pragma unroll
                for (int j = 0; j < 4; ++j) acc[i][j] = fmaf(a[i], bb[j], acc[i][j]);
        }
        __syncthreads();
    }
    const float4 bv = *(const float4*)&bias[n0 + tx * 4];
    const float bj[4] = {bv.x, bv.y, bv.z, bv.w};
#pragma unroll
    for (int j = 0; j < 4; ++j) {
        int n = n0 + tx * 4 + j;
        float4 v = make_float4(acc[0][j] + bj[j], acc[1][j] + bj[j],
                               acc[2][j] + bj[j], acc[3][j] + bj[j]);
        *(float4*)&g_HT[n * N_NODES + m0 + ty * 4] = v;
    }
}

// Raw per-graph stats {sum, sumsq, max, min} per column from transposed H.
// Block per graph, 384 threads = (col, node-half); contiguous streaming reads.
__global__ void k_pool(const int* __restrict__ batch) {
    __shared__ int sse[2];
    __shared__ float4 redh[DOUT];
    int g = blockIdx.x, t = threadIdx.x;        // 384
    int c = t % DOUT, h = t / DOUT;
    if (t < 2) {
        int target = g + t;
        int lo = 0, hi = N_NODES;
        while (lo < hi) {
            int mid = (lo + hi) >> 1;
            if (batch[mid] < target) lo = mid + 1; else hi = mid;
        }
        sse[t] = lo;
    }
    __syncthreads();
    int s = sse[0], e = sse[1];
    int mid = (s + e) >> 1;
    int b0 = h ? mid : s, b1 = h ? e : mid;
    const float* row = &g_HT[c * N_NODES];
    float sum = 0.f, ssq = 0.f, mx = -CUDART_INF_F, mn = CUDART_INF_F;
    int r = b0;
    for (; r + 3 < b1; r += 4) {
        float v0 = row[r], v1 = row[r + 1], v2 = row[r + 2], v3 = row[r + 3];
        sum += v0 + v1 + v2 + v3;
        ssq += v0 * v0 + v1 * v1 + v2 * v2 + v3 * v3;
        mx = fmaxf(mx, fmaxf(fmaxf(v0, v1), fmaxf(v2, v3)));
        mn = fminf(mn, fminf(fminf(v0, v1), fminf(v2, v3)));
    }
    for (; r < b1; ++r) {
        float v = row[r];
        sum += v; ssq += v * v;
        mx = fmaxf(mx, v); mn = fminf(mn, v);
    }
    if (h == 1) redh[c] = make_float4(sum, ssq, mx, mn);
    __syncthreads();
    if (h == 0) {
        float4 o = redh[c];
        sum += o.x; ssq += o.y;
        mx = fmaxf(mx, o.z); mn = fminf(mn, o.w);
        g_pool[g * DOUT + c] = make_float4(sum, ssq, mx, mn);
    }
}

// BN1-finalize (analytic) + triple pooling + bn2 + fc1 + fc2 + fc3 +
// log_softmax + scratch re-zero. 16 blocks x 384 threads, 4 graphs per block.
__global__ void k_funnel(const int* __restrict__ batch,
                         const float* __restrict__ g1, const float* __restrict__ be1,
                         const float* __restrict__ g2, const float* __restrict__ be2,
                         const float* __restrict__ w1, const float* __restrict__ b1,
                         const float* __restrict__ w2, const float* __restrict__ b2,
                         const float* __restrict__ w3, const float* __restrict__ b3,
                         float* __restrict__ out) {
    __shared__ int   s_seg[G_GRAPHS + 1];
    __shared__ float s_cnt[G_GRAPHS];
    __shared__ float sa1[DOUT], so1[DOUT];
    __shared__ float sx[4][D3];
    __shared__ float a1s[4][H1DIM];
    __shared__ float a2s[4][H2DIM];
    int tid = threadIdx.x;                      // 384
    int r0 = blockIdx.x * 4;

    if (tid <= G_GRAPHS) {
        int lo = 0, hi = N_NODES;
        while (lo < hi) {
            int mid = (lo + hi) >> 1;
            if (batch[mid] < tid) lo = mid + 1; else hi = mid;
        }
        s_seg[tid] = lo;
    }
    __syncthreads();
    if (tid < G_GRAPHS) s_cnt[tid] = (float)(s_seg[tid + 1] - s_seg[tid]);
    // BN1 global stats from per-graph partials: a = gamma*rstd, off = beta - a*mu
    if (tid < DOUT) {
        float S = 0.f, SS = 0.f;
        for (int g = 0; g < G_GRAPHS; ++g) {
            float4 p = g_pool[g * DOUT + tid];
            S += p.x; SS += p.y;
        }
        float mu = S * (1.0f / N_NODES);
        float var = SS * (1.0f / N_NODES) - mu * mu;
        float a = g1[tid] * rsqrtf(var + BN_EPS);
        sa1[tid] = a;
        so1[tid] = be1[tid] - a * mu;
    }
    __syncthreads();

    // build Hg per column on the fly; bn2 stats + stash our 4 rows
    for (int c = tid; c < D3; c += 384) {
        int cc = c % DOUT;
        int type = c / DOUT;                    // 0=avg 1=sum 2=max
        float a = sa1[cc], off = so1[cc];
        float s = 0.f, ss = 0.f;
        for (int g = 0; g < G_GRAPHS; ++g) {
            float4 p = g_pool[g * DOUT + cc];
            float val;
            if (type == 2) {
                val = (a >= 0.f) ? fmaf(a, p.z, off) : fmaf(a, p.w, off);
            } else {
                float sv = fmaf(a, p.x, s_cnt[g] * off);
                val = type ? sv : sv / fmaxf(s_cnt[g], 1.f);
            }
            s += val; ss += val * val;
            int r = g - r0;
            if ((unsigned)r < 4u) sx[r][c] = val;
        }
        float mu2 = s * (1.0f / G_GRAPHS);
        float var2 = ss * (1.0f / G_GRAPHS) - mu2 * mu2;
        float rs2 = rsqrtf(var2 + BN_EPS);
        float ga2 = g2[c], bb2 = be2[c];
#pragma unroll
        for (int r = 0; r < 4; ++r)
            sx[r][c] = ga2 * (sx[r][c] - mu2) * rs2 + bb2;
    }
    __syncthreads();
    // fc1: 384 outs
    {
        int o = tid;
        float a0 = b1[o], a1 = a0, a2 = a0, a3 = a0;
        const float4* wr = (const float4*)&w1[o * D3];
#pragma unroll 4
        for (int k4 = 0; k4 < D3 / 4; ++k4) {
            float4 w = wr[k4];
            int k = k4 * 4;
            a0 += w.x * sx[0][k] + w.y * sx[0][k + 1] + w.z * sx[0][k + 2] + w.w * sx[0][k + 3];
            a1 += w.x * sx[1][k] + w.y * sx[1][k + 1] + w.z * sx[1][k + 2] + w.w * sx[1][k + 3];
            a2 += w.x * sx[2][k] + w.y * sx[2][k + 1] + w.z * sx[2][k + 2] + w.w * sx[2][k + 3];
            a3 += w.x * sx[3][k] + w.y * sx[3][k + 1] + w.z * sx[3][k + 2] + w.w * sx[3][k + 3];
        }
        a1s[0][o] = fmaxf(a0, 0.f);
        a1s[1][o] = fmaxf(a1, 0.f);
        a1s[2][o] = fmaxf(a2, 0.f);
        a1s[3][o] = fmaxf(a3, 0.f);
    }
    __syncthreads();
    // fc2: 192 outs
    if (tid < H2DIM) {
        int o = tid;
        float a0 = b2[o], a1 = a0, a2 = a0, a3 = a0;
        const float4* wr = (const float4*)&w2[o * H1DIM];
#pragma unroll 4
        for (int k4 = 0; k4 < H1DIM / 4; ++k4) {
            float4 w = wr[k4];
            int k = k4 * 4;
            a0 += w.x * a1s[0][k] + w.y * a1s[0][k + 1] + w.z * a1s[0][k + 2] + w.w * a1s[0][k + 3];
            a1 += w.x * a1s[1][k] + w.y * a1s[1][k + 1] + w.z * a1s[1][k + 2] + w.w * a1s[1][k + 3];
            a2 += w.x * a1s[2][k] + w.y * a1s[2][k + 1] + w.z * a1s[2][k + 2] + w.w * a1s[2][k + 3];
            a3 += w.x * a1s[3][k] + w.y * a1s[3][k + 1] + w.z * a1s[3][k + 2] + w.w * a1s[3][k + 3];
        }
        a2s[0][o] = fmaxf(a0, 0.f);
        a2s[1][o] = fmaxf(a1, 0.f);
        a2s[2][o] = fmaxf(a2, 0.f);
        a2s[3][o] = fmaxf(a3, 0.f);
    }
    __syncthreads();
    // fc3 + log_softmax: warp w handles graph r0+w
    if (tid < 128) {
        int wrp = tid >> 5, lane = tid & 31;
        float z = -CUDART_INF_F;
        if (lane < NCLS) {
            z = b3[lane];
            const float* wr = &w3[lane * H2DIM];
            for (int k = 0; k < H2DIM; ++k) z = fmaf(wr[k], a2s[wrp][k], z);
        }
        float mx = z;
#pragma unroll
        for (int off = 16; off; off >>= 1) mx = fmaxf(mx, __shfl_xor_sync(0xffffffff, mx, off));
        float ex = (lane < NCLS) ? expf(z - mx) : 0.f;
        float sm = ex;
#pragma unroll
        for (int off = 16; off; off >>= 1) sm += __shfl_xor_sync(0xffffffff, sm, off);
        if (lane < NCLS) out[(r0 + wrp) * NCLS + lane] = z - mx - logf(sm);
    }
    // tail: re-zero scratch for next replay
    int gidx = blockIdx.x * 384 + tid;
    for (int i = gidx; i < N_NODES; i += 16 * 384) {
        g_deg[i] = 0.f;
        g_rowCnt[i] = 0;
    }
}

// ---------------- launch ----------------
extern "C" void kernel_launch(void* const* d_in, const int* in_sizes, int n_in,
                              void* d_out, int out_size) {
    const float* x     = (const float*)d_in[0];
    const int*   ei    = (const int*)d_in[1];
    const int*   batch = (const int*)d_in[2];
    const float* Wo    = (const float*)d_in[3];
    const float* b     = (const float*)d_in[4];
    const float* u     = (const float*)d_in[5];
    const float* bn1g  = (const float*)d_in[6];
    const float* bn1b  = (const float*)d_in[7];
    const float* bn2g  = (const float*)d_in[8];
    const float* bn2b  = (const float*)d_in[9];
    const float* w1    = (const float*)d_in[10];
    const float* b1    = (const float*)d_in[11];
    const float* w2    = (const float*)d_in[12];
    const float* b2    = (const float*)d_in[13];
    const float* w3    = (const float*)d_in[14];
    const float* b3    = (const float*)d_in[15];
    float*       out   = (float*)d_out;

    k_degree<<<N_EDGES / 256, 256>>>(ei);
    k_scan<<<1, 1024>>>(Wo, u);
    k_build<<<N_EDGES / 256, 256>>>(ei);
    k_spmm1<<<N_NODES * 32 / 256, 256>>>(x);
    k_spmm2<<<N_NODES * 32 / 256, 256>>>();
    k_gemm<<<dim3(N_NODES / 64, DOUT / 64), 256>>>(Wo, b);
    k_pool<<<G_GRAPHS, 384>>>(batch);
    k_funnel<<<16, 384>>>(batch, bn1g, bn1b, bn2g, bn2b, w1, b1, w2, b2, w3, b3, out);
}

// round 15
// speedup vs baseline: 1.3056x; 1.3056x over previous
#include <cuda_runtime.h>
#include <math_constants.h>

// ---------------- problem constants (fixed shapes) ----------------
#define N_NODES  8192
#define N_EDGES  262144
#define IN_C     64
#define DIN      192          // IN_C * K
#define DOUT     192          // OUT_C * K
#define G_GRAPHS 64
#define D3       576          // 3 * DOUT
#define H1DIM    384
#define H2DIM    192
#define NCLS     10
#define BN_EPS   1e-5f

// ---------------- device scratch ----------------
__device__ float g_deg[N_NODES];        // zeroed by funnel tail
__device__ int   g_rowCnt[N_NODES];     // zeroed by funnel tail
__device__ float g_dinv[N_NODES];
__device__ int   g_rowPtr[N_NODES + 1];
__device__ unsigned long long g_cv[N_EDGES];   // packed (val<<32 | col)
__device__ float g_Hcat[N_NODES * DIN]; // [x | Lx | L^2 x]
__device__ float g_H[N_NODES * DOUT];   // after masked linear (+bias)
__device__ float g_sigma;
__device__ float g_sum[DOUT], g_sumsq[DOUT];   // BN1 stats (zeroed by funnel tail)
__device__ float g_Hg[G_GRAPHS * D3];   // [avg | sum | max] per graph

// ---------------- kernels ----------------

__global__ void k_degree(const int* __restrict__ ei) {
    int e = blockIdx.x * blockDim.x + threadIdx.x;
    if (e < N_EDGES) atomicAdd(&g_deg[ei[e]], 1.0f);
}

// dinv + exclusive scan (warp-shuffle) + parallel spectral sigma, 1024 threads
__global__ void k_scan(const float* __restrict__ W, const float* __restrict__ u) {
    __shared__ int   wsum[32];
    __shared__ float fred[256];
    __shared__ float vpart[5][DIN];
    int t = threadIdx.x, lane = t & 31, wid = t >> 5;
    int base = t * 8;
    int loc[8]; int s = 0;
#pragma unroll
    for (int j = 0; j < 8; ++j) {
        float d = g_deg[base + j];
        g_dinv[base + j] = (d > 0.f) ? rsqrtf(fmaxf(d, 1.f)) : 0.f;
        loc[j] = s; s += (int)d;
    }
    int isc = s;
#pragma unroll
    for (int off = 1; off < 32; off <<= 1) {
        int v = __shfl_up_sync(0xffffffff, isc, off);
        if (lane >= off) isc += v;
    }
    if (lane == 31) wsum[wid] = isc;
    __syncthreads();
    if (wid == 0) {
        int v = wsum[lane];
        int sc = v;
#pragma unroll
        for (int off = 1; off < 32; off <<= 1) {
            int q = __shfl_up_sync(0xffffffff, sc, off);
            if (lane >= off) sc += q;
        }
        wsum[lane] = sc - v;
    }
    __syncthreads();
    int tbase = wsum[wid] + (isc - s);
#pragma unroll
    for (int j = 0; j < 8; ++j) g_rowPtr[base + j] = tbase + loc[j];
    if (t == 1023) g_rowPtr[N_NODES] = tbase + s;

    // sigma = ||W^T u||^2 / (||W^T u|| + 1e-12); 960 threads, 5-way row split
    if (t < 960) {
        int g = t / DIN, c = t % DIN;
        float a = 0.f;
        for (int i = g; i < DOUT; i += 5)
            a = fmaf(W[i * DIN + c], __ldg(&u[i]), a);
        vpart[g][c] = a;
    }
    __syncthreads();
    float vsq = 0.f;
    if (t < DIN) {
        float v = vpart[0][t] + vpart[1][t] + vpart[2][t] + vpart[3][t] + vpart[4][t];
        vsq = v * v;
    }
    if (t < 256) fred[t] = vsq;
    __syncthreads();
    for (int off = 128; off; off >>= 1) {
        if (t < 256 && t < off) fred[t] += fred[t + off];
        __syncthreads();
    }
    if (t == 0) {
        float ns = fred[0];
        g_sigma = ns / (sqrtf(ns) + 1e-12f);
    }
}

// CSR fill: one packed 8B store per edge
__global__ void k_build(const int* __restrict__ ei) {
    int e = blockIdx.x * blockDim.x + threadIdx.x;
    if (e >= N_EDGES) return;
    int r = ei[e];
    int c = ei[N_EDGES + e];
    float v = -g_dinv[r] * g_dinv[c];
    int pos = g_rowPtr[r] + atomicAdd(&g_rowCnt[r], 1);
    g_cv[pos] = ((unsigned long long)__float_as_uint(v) << 32) | (unsigned int)c;
}

// SpMM body: software-pipelined 4-edge groups (prefetch next cv group before
// issuing current gathers -> cv loads overlap gather latency).
template <int STRIDE>
__device__ __forceinline__ float2 spmm_row(const float* __restrict__ src,
                                           float2 acc, int s, int e) {
    int n4 = (e - s) >> 2;
    int p = s;
    if (n4 > 0) {
        unsigned long long a0 = __ldg(&g_cv[p]),     a1 = __ldg(&g_cv[p + 1]);
        unsigned long long a2 = __ldg(&g_cv[p + 2]), a3 = __ldg(&g_cv[p + 3]);
        for (int gq = 0; gq < n4; ++gq) {
            unsigned long long b0 = a0, b1 = a1, b2 = a2, b3 = a3;
            p += 4;
            if (gq + 1 < n4) {
                a0 = __ldg(&g_cv[p]);     a1 = __ldg(&g_cv[p + 1]);
                a2 = __ldg(&g_cv[p + 2]); a3 = __ldg(&g_cv[p + 3]);
            }
            float2 x0 = *(const float2*)&src[(int)(b0 & 0xffffffffu) * STRIDE];
            float2 x1 = *(const float2*)&src[(int)(b1 & 0xffffffffu) * STRIDE];
            float2 x2 = *(const float2*)&src[(int)(b2 & 0xffffffffu) * STRIDE];
            float2 x3 = *(const float2*)&src[(int)(b3 & 0xffffffffu) * STRIDE];
            float v0 = __uint_as_float((unsigned)(b0 >> 32));
            float v1 = __uint_as_float((unsigned)(b1 >> 32));
            float v2 = __uint_as_float((unsigned)(b2 >> 32));
            float v3 = __uint_as_float((unsigned)(b3 >> 32));
            acc.x = fmaf(v0, x0.x, acc.x); acc.y = fmaf(v0, x0.y, acc.y);
            acc.x = fmaf(v1, x1.x, acc.x); acc.y = fmaf(v1, x1.y, acc.y);
            acc.x = fmaf(v2, x2.x, acc.x); acc.y = fmaf(v2, x2.y, acc.y);
            acc.x = fmaf(v3, x3.x, acc.x); acc.y = fmaf(v3, x3.y, acc.y);
        }
    }
    for (; p < e; ++p) {
        unsigned long long cv = __ldg(&g_cv[p]);
        float v = __uint_as_float((unsigned)(cv >> 32));
        float2 a = *(const float2*)&src[(int)(cv & 0xffffffffu) * STRIDE];
        acc.x = fmaf(v, a.x, acc.x); acc.y = fmaf(v, a.y, acc.y);
    }
    return acc;
}

// hop 1: Hcat[:,0:64]=x, Hcat[:,64:128]=x+L_off@x  (warp/row)
__global__ void __launch_bounds__(256, 4) k_spmm1(const float* __restrict__ x) {
    int w = (blockIdx.x * blockDim.x + threadIdx.x) >> 5;
    int lane = threadIdx.x & 31;
    const float* src = &x[2 * lane];
    float2 xv0 = *(const float2*)&src[w * 64];
    float2 acc = spmm_row<64>(src, xv0, g_rowPtr[w], g_rowPtr[w + 1]);
    *(float2*)&g_Hcat[w * DIN + 2 * lane]      = xv0;
    *(float2*)&g_Hcat[w * DIN + 64 + 2 * lane] = acc;
}

// hop 2: src = Hcat[:,64:128], dst = Hcat[:,128:192]
__global__ void __launch_bounds__(256, 4) k_spmm2() {
    int w = (blockIdx.x * blockDim.x + threadIdx.x) >> 5;
    int lane = threadIdx.x & 31;
    const float* src = &g_Hcat[64 + 2 * lane];
    float2 acc0 = *(const float2*)&src[w * DIN];
    float2 acc = spmm_row<DIN>(src, acc0, g_rowPtr[w], g_rowPtr[w + 1]);
    *(float2*)&g_Hcat[w * DIN + 128 + 2 * lane] = acc;
}

// H = Hcat @ (mask(W)/sigma)^T + b, mask folded into Klim.
// float4 shared reads (rows padded to 68 floats = 16B-aligned).
// Fused BN1 column-stat accumulation via smem + global atomics.
__global__ void k_gemm(const float* __restrict__ W, const float* __restrict__ bias) {
    const int m0 = blockIdx.x * 64;
    const int n0 = blockIdx.y * 64;
    const int Klim = 64 * (blockIdx.y + 1);
    __shared__ float As[32][68];
    __shared__ float Bs[32][68];
    __shared__ float s_s[64], s_ss[64];
    const int tid = threadIdx.x;                // 256
    const int tx = tid & 15, ty = tid >> 4;
    const float invSig = 1.0f / g_sigma;
    float acc[4][4] = {};
    for (int k0 = 0; k0 < Klim; k0 += 32) {
#pragma unroll
        for (int r = 0; r < 8; ++r) {
            int e = tid + r * 256;
            int m = e >> 5, k = e & 31;
            As[k][m] = g_Hcat[(m0 + m) * DIN + k0 + k];
            Bs[k][m] = W[(n0 + m) * DIN + k0 + k] * invSig;
        }
        __syncthreads();
#pragma unroll
        for (int k = 0; k < 32; ++k) {
            float4 av = *(const float4*)&As[k][ty * 4];
            float4 bv = *(const float4*)&Bs[k][tx * 4];
            float a[4] = {av.x, av.y, av.z, av.w};
            float bb[4] = {bv.x, bv.y, bv.z, bv.w};
#pragma unroll
            for (int i = 0; i < 4; ++i)
#pragma unroll
                for (int j = 0; j < 4; ++j) acc[i][j] = fmaf(a[i], bb[j], acc[i][j]);
        }
        __syncthreads();
    }
    if (tid < 64) { s_s[tid] = 0.f; s_ss[tid] = 0.f; }
    __syncthreads();
#pragma unroll
    for (int j = 0; j < 4; ++j) {
        int n = n0 + tx * 4 + j;
        float bv = bias[n];
        float cs = 0.f, css = 0.f;
#pragma unroll
        for (int i = 0; i < 4; ++i) {
            int m = m0 + ty * 4 + i;
            float v = acc[i][j] + bv;
            g_H[m * DOUT + n] = v;
            cs += v; css += v * v;
        }
        atomicAdd(&s_s[tx * 4 + j], cs);
        atomicAdd(&s_ss[tx * 4 + j], css);
    }
    __syncthreads();
    if (tid < 64) {
        atomicAdd(&g_sum[n0 + tid], s_s[tid]);
        atomicAdd(&g_sumsq[n0 + tid], s_ss[tid]);
    }
}

// BN1(apply) + segment avg/sum/max; 384 threads = 2 row-halves per column
__global__ void k_pool(const int* __restrict__ batch,
                       const float* __restrict__ gamma, const float* __restrict__ beta) {
    __shared__ int sse[2];
    __shared__ float s_sum[DOUT], s_max[DOUT];
    int g = blockIdx.x;
    int t = threadIdx.x;                        // 384
    int c = t % DOUT, h = t / DOUT;
    if (t < 2) {
        int target = g + t;
        int lo = 0, hi = N_NODES;
        while (lo < hi) {
            int mid = (lo + hi) >> 1;
            if (batch[mid] < target) lo = mid + 1; else hi = mid;
        }
        sse[t] = lo;
    }
    __syncthreads();
    int s = sse[0], e = sse[1];
    float mu = g_sum[c] * (1.0f / N_NODES);
    float var = g_sumsq[c] * (1.0f / N_NODES) - mu * mu;
    float rs = rsqrtf(var + BN_EPS);
    float ga = gamma[c], be = beta[c];
    float a = ga * rs, off = be - a * mu;       // v = a*h + off
    float sum = 0.f, mx = -CUDART_INF_F;
#pragma unroll 8
    for (int r = s + h; r < e; r += 2) {
        float v = fmaf(a, g_H[r * DOUT + c], off);
        sum += v;
        mx = fmaxf(mx, v);
    }
    if (h == 1) { s_sum[c] = sum; s_max[c] = mx; }
    __syncthreads();
    if (h == 0) {
        sum += s_sum[c];
        mx = fmaxf(mx, s_max[c]);
        float cnt = (float)(e - s);
        g_Hg[g * D3 + c]            = sum / fmaxf(cnt, 1.f);
        g_Hg[g * D3 + DOUT + c]     = sum;
        g_Hg[g * D3 + 2 * DOUT + c] = mx;
    }
}

// bn2 + fc1 + fc2 + fc3 + log_softmax + scratch re-zero (16 blocks x 384)
__global__ void k_funnel(const float* __restrict__ g2, const float* __restrict__ be2,
                         const float* __restrict__ w1, const float* __restrict__ b1,
                         const float* __restrict__ w2, const float* __restrict__ b2,
                         const float* __restrict__ w3, const float* __restrict__ b3,
                         float* __restrict__ out) {
    __shared__ float smu[D3], srs[D3];
    __shared__ float sx[4][D3];
    __shared__ float a1s[4][H1DIM];
    __shared__ float a2s[4][H2DIM];
    int tid = threadIdx.x;                      // 384
    int r0 = blockIdx.x * 4;

    for (int c = tid; c < D3; c += 384) {
        float s = 0.f, ss = 0.f;
        for (int r = 0; r < G_GRAPHS; ++r) {
            float v = g_Hg[r * D3 + c];
            s += v; ss += v * v;
        }
        float mu = s * (1.0f / G_GRAPHS);
        float var = ss * (1.0f / G_GRAPHS) - mu * mu;
        smu[c] = mu;
        srs[c] = rsqrtf(var + BN_EPS);
    }
    __syncthreads();
    for (int e = tid; e < 4 * D3; e += 384) {
        int r = e / D3, c = e % D3;
        sx[r][c] = g2[c] * (g_Hg[(r0 + r) * D3 + c] - smu[c]) * srs[c] + be2[c];
    }
    __syncthreads();
    {
        int o = tid;
        float a0 = b1[o], a1 = a0, a2 = a0, a3 = a0;
        const float4* wr = (const float4*)&w1[o * D3];
#pragma unroll 4
        for (int k4 = 0; k4 < D3 / 4; ++k4) {
            float4 w = wr[k4];
            int k = k4 * 4;
            a0 += w.x * sx[0][k] + w.y * sx[0][k + 1] + w.z * sx[0][k + 2] + w.w * sx[0][k + 3];
            a1 += w.x * sx[1][k] + w.y * sx[1][k + 1] + w.z * sx[1][k + 2] + w.w * sx[1][k + 3];
            a2 += w.x * sx[2][k] + w.y * sx[2][k + 1] + w.z * sx[2][k + 2] + w.w * sx[2][k + 3];
            a3 += w.x * sx[3][k] + w.y * sx[3][k + 1] + w.z * sx[3][k + 2] + w.w * sx[3][k + 3];
        }
        a1s[0][o] = fmaxf(a0, 0.f);
        a1s[1][o] = fmaxf(a1, 0.f);
        a1s[2][o] = fmaxf(a2, 0.f);
        a1s[3][o] = fmaxf(a3, 0.f);
    }
    __syncthreads();
    if (tid < H2DIM) {
        int o = tid;
        float a0 = b2[o], a1 = a0, a2 = a0, a3 = a0;
        const float4* wr = (const float4*)&w2[o * H1DIM];
#pragma unroll 4
        for (int k4 = 0; k4 < H1DIM / 4; ++k4) {
            float4 w = wr[k4];
            int k = k4 * 4;
            a0 += w.x * a1s[0][k] + w.y * a1s[0][k + 1] + w.z * a1s[0][k + 2] + w.w * a1s[0][k + 3];
            a1 += w.x * a1s[1][k] + w.y * a1s[1][k + 1] + w.z * a1s[1][k + 2] + w.w * a1s[1][k + 3];
            a2 += w.x * a1s[2][k] + w.y * a1s[2][k + 1] + w.z * a1s[2][k + 2] + w.w * a1s[2][k + 3];
            a3 += w.x * a1s[3][k] + w.y * a1s[3][k + 1] + w.z * a1s[3][k + 2] + w.w * a1s[3][k + 3];
        }
        a2s[0][o] = fmaxf(a0, 0.f);
        a2s[1][o] = fmaxf(a1, 0.f);
        a2s[2][o] = fmaxf(a2, 0.f);
        a2s[3][o] = fmaxf(a3, 0.f);
    }
    __syncthreads();
    if (tid < 128) {
        int wrp = tid >> 5, lane = tid & 31;
        float z = -CUDART_INF_F;
        if (lane < NCLS) {
            z = b3[lane];
            const float* wr = &w3[lane * H2DIM];
            for (int k = 0; k < H2DIM; ++k) z = fmaf(wr[k], a2s[wrp][k], z);
        }
        float mx = z;
#pragma unroll
        for (int off = 16; off; off >>= 1) mx = fmaxf(mx, __shfl_xor_sync(0xffffffff, mx, off));
        float ex = (lane < NCLS) ? expf(z - mx) : 0.f;
        float sm = ex;
#pragma unroll
        for (int off = 16; off; off >>= 1) sm += __shfl_xor_sync(0xffffffff, sm, off);
        if (lane < NCLS) out[(r0 + wrp) * NCLS + lane] = z - mx - logf(sm);
    }
    int gidx = blockIdx.x * 384 + tid;
    for (int i = gidx; i < N_NODES; i += 16 * 384) {
        g_deg[i] = 0.f;
        g_rowCnt[i] = 0;
    }
    if (gidx < DOUT) { g_sum[gidx] = 0.f; g_sumsq[gidx] = 0.f; }
}

// ---------------- launch ----------------
extern "C" void kernel_launch(void* const* d_in, const int* in_sizes, int n_in,
                              void* d_out, int out_size) {
    const float* x     = (const float*)d_in[0];
    const int*   ei    = (const int*)d_in[1];
    const int*   batch = (const int*)d_in[2];
    const float* Wo    = (const float*)d_in[3];
    const float* b     = (const float*)d_in[4];
    const float* u     = (const float*)d_in[5];
    const float* bn1g  = (const float*)d_in[6];
    const float* bn1b  = (const float*)d_in[7];
    const float* bn2g  = (const float*)d_in[8];
    const float* bn2b  = (const float*)d_in[9];
    const float* w1    = (const float*)d_in[10];
    const float* b1    = (const float*)d_in[11];
    const float* w2    = (const float*)d_in[12];
    const float* b2    = (const float*)d_in[13];
    const float* w3    = (const float*)d_in[14];
    const float* b3    = (const float*)d_in[15];
    float*       out   = (float*)d_out;

    k_degree<<<N_EDGES / 256, 256>>>(ei);
    k_scan<<<1, 1024>>>(Wo, u);
    k_build<<<N_EDGES / 256, 256>>>(ei);
    k_spmm1<<<N_NODES * 32 / 256, 256>>>(x);
    k_spmm2<<<N_NODES * 32 / 256, 256>>>();
    k_gemm<<<dim3(N_NODES / 64, DOUT / 64), 256>>>(Wo, b);
    k_pool<<<G_GRAPHS, 384>>>(batch, bn1g, bn1b);
    k_funnel<<<16, 384>>>(bn2g, bn2b, w1, b1, w2, b2, w3, b3, out);
}